// round 16
// baseline (speedup 1.0000x reference)
#include <cuda_runtime.h>
#include <cuda_bf16.h>
#include <math.h>
#include <float.h>
#include <stdint.h>

#define BN_ 65536     // rows
#define D_  256       // dim
#define K_  1024      // codes
#define CAPR  24      // per-row candidate pool slots
#define WINDOW 3.5e-4f

// ---------------- device scratch ----------------
__device__ float         g_xnorm[BN_];
__device__ float         g_enorm[K_];
__device__ __nv_bfloat16 g_ebf[K_ * D_];
__device__ int           g_best_i[BN_];
__device__ int           g_ncand[BN_];
__device__ int           g_cand[BN_ * CAPR];
__device__ int           g_counts[K_];
__device__ double        g_loss;

__device__ __forceinline__ uint32_t smem_u32(const void* p) {
    uint32_t a;
    asm("{ .reg .u64 t; cvta.to.shared.u64 t, %1; cvt.u32.u64 %0, t; }" : "=r"(a) : "l"(p));
    return a;
}
#define STS128(addr, r0, r1, r2, r3) \
    asm volatile("st.shared.v4.b32 [%0], {%1, %2, %3, %4};" :: "r"(addr), "r"(r0), "r"(r1), "r"(r2), "r"(r3) : "memory")
#define LDSM_X4(r0, r1, r2, r3, addr) \
    asm volatile("ldmatrix.sync.aligned.m8n8.x4.shared.b16 {%0,%1,%2,%3}, [%4];" \
        : "=r"(r0), "=r"(r1), "=r"(r2), "=r"(r3) : "r"(addr))
#define MMA_BF16(d, a, b) \
    asm volatile("mma.sync.aligned.m16n8k16.row.col.f32.bf16.bf16.f32 " \
        "{%0,%1,%2,%3}, {%4,%5,%6,%7}, {%8,%9}, {%0,%1,%2,%3};" \
        : "+f"((d)[0]), "+f"((d)[1]), "+f"((d)[2]), "+f"((d)[3]) \
        : "r"((a)[0]), "r"((a)[1]), "r"((a)[2]), "r"((a)[3]), "r"((b)[0]), "r"((b)[1]))

// smem layout (dynamic)
#define SM_X    0          // 128 rows x 512B = 65536
#define SM_E    65536      // 64 codes x 512B = 32768
#define SM_EN   98304      // 64 f32
#define SM_CNT  98560      // 128 ints
#define SM_POOL 99072      // 128 x CAPR ints = 12288
#define SM_XN   111360     // 128 f32
#define SMEM_BYTES 111872

// ---------------------------------------------------------------------------
// Prep (E only): row norms + fp32->bf16 conversion. One warp per code row.
// ---------------------------------------------------------------------------
__global__ void enorm_kernel(const float* __restrict__ E) {
    int k    = (blockIdx.x * blockDim.x + threadIdx.x) >> 5;
    int lane = threadIdx.x & 31;
    if (k >= K_) return;
    const float4* p = (const float4*)(E + (size_t)k * D_);
    float4 a = p[lane], b = p[lane + 32];
    __nv_bfloat162* eb = (__nv_bfloat162*)g_ebf;
    eb[k*128 + 2*lane + 0]  = __float22bfloat162_rn(make_float2(a.x, a.y));
    eb[k*128 + 2*lane + 1]  = __float22bfloat162_rn(make_float2(a.z, a.w));
    eb[k*128 + 64 + 2*lane] = __float22bfloat162_rn(make_float2(b.x, b.y));
    eb[k*128 + 65 + 2*lane] = __float22bfloat162_rn(make_float2(b.z, b.w));
    float s = a.x*a.x + a.y*a.y + a.z*a.z + a.w*a.w
            + b.x*b.x + b.y*b.y + b.z*b.z + b.w*b.w;
#pragma unroll
    for (int o = 16; o; o >>= 1) s += __shfl_xor_sync(0xffffffffu, s, o);
    if (lane == 0) g_enorm[k] = s;
}

__global__ void zero_kernel() {
    int t = threadIdx.x;
    g_counts[t] = 0;
    if (t == 0) g_loss = 0.0;
}

// ---------------------------------------------------------------------------
// Main: bf16 mma.sync distance GEMM + windowed candidate capture into a
// per-row shared pool. Epilogue uses a chunk-min fast path: a tree-min over
// the 16 per-track distances gates the serial capture scan (conservative
// trigger; skipped chunks are provably no-ops).
// ---------------------------------------------------------------------------
__global__ __launch_bounds__(128)
void vq_mma_kernel(const float* __restrict__ X) {
    extern __shared__ char smem[];
    const uint32_t sb = smem_u32(smem);
    const int tid  = threadIdx.x;
    const int wid  = tid >> 5;
    const int lane = tid & 31;
    const int row0 = blockIdx.x * 128;
    const int gid  = lane >> 2;        // 0..7
    const int tig  = lane & 3;         // 0..3

    int*   scnt  = (int*)(smem + SM_CNT);
    int*   spool = (int*)(smem + SM_POOL);
    float* sxn   = (float*)(smem + SM_XN);
    if (tid < 128) scnt[tid] = 0;

    // ---- fill X tile (fp32 -> bf16, XOR-swizzled) + in-flight row norms ----
#pragma unroll 4
    for (int it = 0; it < 32; ++it) {
        int v  = it * 128 + tid;
        int r  = v >> 5;               // uniform across the warp
        int cv = v & 31;
        const float4* gp = (const float4*)(X + (size_t)(row0 + r) * D_ + cv * 8);
        float4 A = gp[0], B = gp[1];
        __nv_bfloat162 h0 = __float22bfloat162_rn(make_float2(A.x, A.y));
        __nv_bfloat162 h1 = __float22bfloat162_rn(make_float2(A.z, A.w));
        __nv_bfloat162 h2 = __float22bfloat162_rn(make_float2(B.x, B.y));
        __nv_bfloat162 h3 = __float22bfloat162_rn(make_float2(B.z, B.w));
        uint32_t off = (uint32_t)(r * 512) + (((uint32_t)(cv * 16)) ^ (((uint32_t)(r & 7)) << 4));
        STS128(sb + SM_X + off, *(uint32_t*)&h0, *(uint32_t*)&h1, *(uint32_t*)&h2, *(uint32_t*)&h3);
        float s = A.x*A.x + A.y*A.y + A.z*A.z + A.w*A.w
                + B.x*B.x + B.y*B.y + B.z*B.z + B.w*B.w;
#pragma unroll
        for (int o = 16; o; o >>= 1) s += __shfl_xor_sync(0xffffffffu, s, o);
        if (lane == 0) { sxn[r] = s; g_xnorm[row0 + r] = s; }
    }

    const uint32_t swz     = ((uint32_t)(lane & 7)) << 4;
    const int      rowoffA = (lane & 7) + 8 * ((lane >> 3) & 1);
    const uint32_t kboffA  = 16u * (uint32_t)(lane >> 4);
    const int      rowoffB = (lane & 7) + 8 * (lane >> 4);
    const uint32_t kboffB  = 16u * (uint32_t)((lane >> 3) & 1);

    uint32_t aBase[2], bBase[4];
#pragma unroll
    for (int mb = 0; mb < 2; ++mb)
        aBase[mb] = sb + SM_X + (uint32_t)((wid * 32 + mb * 16 + rowoffA) * 512);
#pragma unroll
    for (int p = 0; p < 4; ++p)
        bBase[p] = sb + SM_E + (uint32_t)((p * 16 + rowoffB) * 512);

    __syncthreads();   // sxn + X tile visible to all

    float v1[4];
    int   i1[4];
    float xn[4];
    int   rl[4];
#pragma unroll
    for (int t = 0; t < 4; ++t) {
        rl[t] = wid * 32 + (t >> 1) * 16 + (t & 1) * 8 + gid;
        v1[t] = FLT_MAX;
        i1[t] = 0;
        xn[t] = sxn[rl[t]];
    }
    float* ens = (float*)(smem + SM_EN);

    for (int nt = 0; nt < 16; ++nt) {
        __syncthreads();
#pragma unroll 4
        for (int it = 0; it < 16; ++it) {
            int v  = it * 128 + tid;
            int r  = v >> 5;
            int cv = v & 31;
            uint4 w = ((const uint4*)(g_ebf + (size_t)(nt * 64 + r) * D_))[cv];
            uint32_t off = (uint32_t)(r * 512) + (((uint32_t)(cv * 16)) ^ (((uint32_t)(r & 7)) << 4));
            STS128(sb + SM_E + off, w.x, w.y, w.z, w.w);
        }
        if (tid < 64) ens[tid] = g_enorm[nt * 64 + tid];
        __syncthreads();

        float acc[2][8][4];
#pragma unroll
        for (int mb = 0; mb < 2; ++mb)
#pragma unroll
            for (int nb = 0; nb < 8; ++nb)
#pragma unroll
                for (int q = 0; q < 4; ++q) acc[mb][nb][q] = 0.f;

#pragma unroll
        for (int s = 0; s < 16; ++s) {
            uint32_t a[2][4], b[4][4];
            uint32_t offA = ((uint32_t)(32 * s) + kboffA) ^ swz;
            uint32_t offB = ((uint32_t)(32 * s) + kboffB) ^ swz;
#pragma unroll
            for (int mb = 0; mb < 2; ++mb)
                LDSM_X4(a[mb][0], a[mb][1], a[mb][2], a[mb][3], aBase[mb] + offA);
#pragma unroll
            for (int p = 0; p < 4; ++p)
                LDSM_X4(b[p][0], b[p][1], b[p][2], b[p][3], bBase[p] + offB);
#pragma unroll
            for (int mb = 0; mb < 2; ++mb)
#pragma unroll
                for (int p = 0; p < 4; ++p) {
                    MMA_BF16(acc[mb][2*p + 0], a[mb], &b[p][0]);
                    MMA_BF16(acc[mb][2*p + 1], a[mb], &b[p][2]);
                }
        }

        // ---- epilogue: per-track distance vector + tree-min fast path ----
#pragma unroll
        for (int t = 0; t < 4; ++t) {
            const int mb = t >> 1;
            const int h  = t & 1;
            float dd[16];
#pragma unroll
            for (int nb = 0; nb < 8; ++nb) {
                float2 enp = *(const float2*)&ens[nb * 8 + 2 * tig];
                dd[nb*2 + 0] = __fadd_rn(__fadd_rn(xn[t], enp.x), -2.0f * acc[mb][nb][h*2 + 0]);
                dd[nb*2 + 1] = __fadd_rn(__fadd_rn(xn[t], enp.y), -2.0f * acc[mb][nb][h*2 + 1]);
            }
            // balanced tree min (no serial dependence chain)
            float m[8];
#pragma unroll
            for (int i = 0; i < 8; ++i) m[i] = fminf(dd[i], dd[i + 8]);
#pragma unroll
            for (int i = 0; i < 4; ++i) m[i] = fminf(m[i], m[i + 4]);
            m[0] = fminf(fminf(m[0], m[1]), fminf(m[2], m[3]));

            if (m[0] < v1[t] + WINDOW) {
                // slow path: original serial capture scan, code-ascending order
#pragma unroll
                for (int i = 0; i < 16; ++i) {
                    int   code = nt * 64 + (i >> 1) * 8 + 2 * tig + (i & 1);
                    float dist = dd[i];
                    if (dist < v1[t] + WINDOW) {
                        if (dist < v1[t]) {
                            if (v1[t] < dist + WINDOW) {
                                int p = atomicAdd(&scnt[rl[t]], 1);
                                if (p < CAPR) spool[rl[t] * CAPR + p] = i1[t];
                            }
                            v1[t] = dist; i1[t] = code;
                        } else {
                            int p = atomicAdd(&scnt[rl[t]], 1);
                            if (p < CAPR) spool[rl[t] * CAPR + p] = code;
                        }
                    }
                }
            }
        }
    }

    // ---- merge across the 4 lanes (tig) sharing each row ----
#pragma unroll
    for (int t = 0; t < 4; ++t) {
        int   row = row0 + rl[t];
        float myv = v1[t];
        int   myi = i1[t];
        float bv  = myv;
        int   bi  = myi;
#pragma unroll
        for (int off = 1; off <= 2; off <<= 1) {
            float vv = __shfl_xor_sync(0xffffffffu, bv, off);
            int   ii = __shfl_xor_sync(0xffffffffu, bi, off);
            if (vv < bv || (vv == bv && ii < bi)) { bv = vv; bi = ii; }
        }
        if (myi != bi && myv < bv + WINDOW) {   // losing lane best within window
            int p = atomicAdd(&scnt[rl[t]], 1);
            if (p < CAPR) spool[rl[t] * CAPR + p] = myi;
        }
        if (tig == 0) g_best_i[row] = bi;
    }
    __syncthreads();
    if (tid < 128) {
        int row = row0 + tid;
        int n   = scnt[tid];
        g_ncand[row] = n;
        int m = n < CAPR ? n : CAPR;
        for (int k = 0; k < m; ++k)
            g_cand[(size_t)row * CAPR + k] = spool[tid * CAPR + k];
    }
}

// ---------------------------------------------------------------------------
// Recheck + gather + loss. 1 warp handles TWO rows interleaved. Batched exact
// fp32 candidate evals, identical argmin semantics. (byte-identical to R13)
// ---------------------------------------------------------------------------
__global__ __launch_bounds__(256) void recheck_kernel(const float* __restrict__ X,
                                                      const float* __restrict__ E,
                                                      float* __restrict__ outq,
                                                      float* __restrict__ out_idx) {
    __shared__ double lsum[8];
    const int tid  = threadIdx.x;
    const int w    = tid >> 5;
    const int lane = tid & 31;
    const int r0   = blockIdx.x * 16 + w * 2;
    const int r1   = r0 + 1;

    const float4* xr0 = (const float4*)(X + (size_t)r0 * D_);
    const float4* xr1 = (const float4*)(X + (size_t)r1 * D_);
    float4 xa0 = xr0[lane * 2], xb0 = xr0[lane * 2 + 1];
    float4 xa1 = xr1[lane * 2], xb1 = xr1[lane * 2 + 1];
    int n0  = g_ncand[r0],  n1  = g_ncand[r1];
    int bi0 = g_best_i[r0], bi1 = g_best_i[r1];

    auto recheck_row = [&](int row, int n, int bi, float4 xa, float4 xb) -> int {
        float xn = g_xnorm[row];
        float bv = FLT_MAX;
        int   bb = 0x7fffffff;
        int   hi   = (n <= CAPR) ? (n + 1) : K_;
        bool  pool = (n <= CAPR);
        const int* gc = g_cand + (size_t)row * CAPR;
        for (int b0 = 0; b0 < hi; b0 += 8) {
            int   c[8];
            float p[8];
#pragma unroll
            for (int j = 0; j < 8; ++j) {
                int idx = b0 + j;
                c[j] = pool ? ((idx < n) ? gc[idx] : bi)
                            : ((idx < K_) ? idx : 0);
                const float4* er = (const float4*)(E + (size_t)c[j] * D_);
                float4 ea = er[lane * 2], eb = er[lane * 2 + 1];
                p[j] = xa.x*ea.x + xa.y*ea.y + xa.z*ea.z + xa.w*ea.w
                     + xb.x*eb.x + xb.y*eb.y + xb.z*eb.z + xb.w*eb.w;
            }
#pragma unroll
            for (int o = 16; o; o >>= 1) {
#pragma unroll
                for (int j = 0; j < 8; ++j)
                    p[j] += __shfl_xor_sync(0xffffffffu, p[j], o);
            }
#pragma unroll
            for (int j = 0; j < 8; ++j) {
                if (b0 + j < hi) {
                    float d = __fadd_rn(__fadd_rn(xn, g_enorm[c[j]]), -2.0f * p[j]);
                    if (d < bv || (d == bv && c[j] < bb)) { bv = d; bb = c[j]; }
                }
            }
        }
        return bb;
    };

    if (n0 > 0) bi0 = recheck_row(r0, n0, bi0, xa0, xb0);
    if (n1 > 0) bi1 = recheck_row(r1, n1, bi1, xa1, xb1);

    const float4* er0 = (const float4*)(E + (size_t)bi0 * D_);
    const float4* er1 = (const float4*)(E + (size_t)bi1 * D_);
    float4 ea0 = er0[lane * 2], eb0 = er0[lane * 2 + 1];
    float4 ea1 = er1[lane * 2], eb1 = er1[lane * 2 + 1];

    float s = 0.f;
    {
        float4 d0, o0, d1, o1;
        d0.x = __fadd_rn(ea0.x, -xa0.x); o0.x = __fadd_rn(xa0.x, d0.x);
        d0.y = __fadd_rn(ea0.y, -xa0.y); o0.y = __fadd_rn(xa0.y, d0.y);
        d0.z = __fadd_rn(ea0.z, -xa0.z); o0.z = __fadd_rn(xa0.z, d0.z);
        d0.w = __fadd_rn(ea0.w, -xa0.w); o0.w = __fadd_rn(xa0.w, d0.w);
        d1.x = __fadd_rn(eb0.x, -xb0.x); o1.x = __fadd_rn(xb0.x, d1.x);
        d1.y = __fadd_rn(eb0.y, -xb0.y); o1.y = __fadd_rn(xb0.y, d1.y);
        d1.z = __fadd_rn(eb0.z, -xb0.z); o1.z = __fadd_rn(xb0.z, d1.z);
        d1.w = __fadd_rn(eb0.w, -xb0.w); o1.w = __fadd_rn(xb0.w, d1.w);
        float4* oq = (float4*)(outq + (size_t)r0 * D_);
        oq[lane * 2]     = o0;
        oq[lane * 2 + 1] = o1;
        s += d0.x*d0.x + d0.y*d0.y + d0.z*d0.z + d0.w*d0.w
           + d1.x*d1.x + d1.y*d1.y + d1.z*d1.z + d1.w*d1.w;
    }
    {
        float4 d0, o0, d1, o1;
        d0.x = __fadd_rn(ea1.x, -xa1.x); o0.x = __fadd_rn(xa1.x, d0.x);
        d0.y = __fadd_rn(ea1.y, -xa1.y); o0.y = __fadd_rn(xa1.y, d0.y);
        d0.z = __fadd_rn(ea1.z, -xa1.z); o0.z = __fadd_rn(xa1.z, d0.z);
        d0.w = __fadd_rn(ea1.w, -xa1.w); o0.w = __fadd_rn(xa1.w, d0.w);
        d1.x = __fadd_rn(eb1.x, -xb1.x); o1.x = __fadd_rn(xb1.x, d1.x);
        d1.y = __fadd_rn(eb1.y, -xb1.y); o1.y = __fadd_rn(xb1.y, d1.y);
        d1.z = __fadd_rn(eb1.z, -xb1.z); o1.z = __fadd_rn(xb1.z, d1.z);
        d1.w = __fadd_rn(eb1.w, -xb1.w); o1.w = __fadd_rn(xb1.w, d1.w);
        float4* oq = (float4*)(outq + (size_t)r1 * D_);
        oq[lane * 2]     = o0;
        oq[lane * 2 + 1] = o1;
        s += d0.x*d0.x + d0.y*d0.y + d0.z*d0.z + d0.w*d0.w
           + d1.x*d1.x + d1.y*d1.y + d1.z*d1.z + d1.w*d1.w;
    }
#pragma unroll
    for (int o = 16; o; o >>= 1) s += __shfl_xor_sync(0xffffffffu, s, o);
    if (lane == 0) {
        lsum[w] = (double)s;
        out_idx[r0] = (float)bi0;
        out_idx[r1] = (float)bi1;
        atomicAdd(&g_counts[bi0], 1);
        atomicAdd(&g_counts[bi1], 1);
    }
    __syncthreads();
    if (tid == 0) {
        double t = 0.0;
#pragma unroll
        for (int i = 0; i < 8; ++i) t += lsum[i];
        atomicAdd(&g_loss, t);
    }
}

// ---------------------------------------------------------------------------
__global__ void final_kernel(float* __restrict__ out_tail) {
    __shared__ float sh[32];
    int t = threadIdx.x;
    float p = (float)g_counts[t] * (1.0f / (float)BN_);
    float term = p * logf(p + 1.1920929e-07f);
#pragma unroll
    for (int o = 16; o; o >>= 1) term += __shfl_xor_sync(0xffffffffu, term, o);
    if ((t & 31) == 0) sh[t >> 5] = term;
    __syncthreads();
    if (t < 32) {
        float v = sh[t];
#pragma unroll
        for (int o = 16; o; o >>= 1) v += __shfl_xor_sync(0xffffffffu, v, o);
        if (t == 0) {
            out_tail[0] = expf(-v);
            out_tail[1] = (float)(g_loss * (1.1 / (double)((size_t)BN_ * D_)));
        }
    }
}

// ---------------------------------------------------------------------------
extern "C" void kernel_launch(void* const* d_in, const int* in_sizes, int n_in,
                              void* d_out, int out_size) {
    const float* X = (const float*)d_in[0];
    const float* E = (const float*)d_in[1];
    float* out      = (float*)d_out;
    float* out_idx  = out + (size_t)BN_ * D_;
    float* out_tail = out_idx + BN_;

    cudaFuncSetAttribute(vq_mma_kernel, cudaFuncAttributeMaxDynamicSharedMemorySize, SMEM_BYTES);

    enorm_kernel<<<K_ / 8, 256>>>(E);
    zero_kernel<<<1, K_>>>();
    vq_mma_kernel<<<BN_ / 128, 128, SMEM_BYTES>>>(X);
    recheck_kernel<<<BN_ / 16, 256>>>(X, E, out, out_idx);
    final_kernel<<<1, K_>>>(out_tail);
}

// round 17
// speedup vs baseline: 1.5434x; 1.5434x over previous
#include <cuda_runtime.h>
#include <cuda_bf16.h>
#include <math.h>
#include <float.h>
#include <stdint.h>

#define BN_ 65536     // rows
#define D_  256       // dim
#define K_  1024      // codes
#define CAPR  24      // per-row candidate pool slots
#define WINDOW 3.5e-4f

// ---------------- device scratch ----------------
__device__ float         g_xnorm[BN_];
__device__ float         g_enorm[K_];
__device__ __nv_bfloat16 g_ebf[K_ * D_];
__device__ int           g_best_i[BN_];
__device__ int           g_ncand[BN_];
__device__ int           g_cand[BN_ * CAPR];
__device__ int           g_counts[K_];
__device__ double        g_loss;

__device__ __forceinline__ uint32_t smem_u32(const void* p) {
    uint32_t a;
    asm("{ .reg .u64 t; cvta.to.shared.u64 t, %1; cvt.u32.u64 %0, t; }" : "=r"(a) : "l"(p));
    return a;
}
#define STS128(addr, r0, r1, r2, r3) \
    asm volatile("st.shared.v4.b32 [%0], {%1, %2, %3, %4};" :: "r"(addr), "r"(r0), "r"(r1), "r"(r2), "r"(r3) : "memory")
#define LDSM_X4(r0, r1, r2, r3, addr) \
    asm volatile("ldmatrix.sync.aligned.m8n8.x4.shared.b16 {%0,%1,%2,%3}, [%4];" \
        : "=r"(r0), "=r"(r1), "=r"(r2), "=r"(r3) : "r"(addr))
#define MMA_BF16(d, a, b) \
    asm volatile("mma.sync.aligned.m16n8k16.row.col.f32.bf16.bf16.f32 " \
        "{%0,%1,%2,%3}, {%4,%5,%6,%7}, {%8,%9}, {%0,%1,%2,%3};" \
        : "+f"((d)[0]), "+f"((d)[1]), "+f"((d)[2]), "+f"((d)[3]) \
        : "r"((a)[0]), "r"((a)[1]), "r"((a)[2]), "r"((a)[3]), "r"((b)[0]), "r"((b)[1]))

// smem layout (dynamic)
#define SM_X    0          // 128 rows x 512B = 65536
#define SM_E    65536      // 64 codes x 512B = 32768
#define SM_EN   98304      // 64 f32
#define SM_CNT  98560      // 128 ints
#define SM_POOL 99072      // 128 x CAPR ints = 12288
#define SM_XN   111360     // 128 f32
#define SMEM_BYTES 111872

// ---------------------------------------------------------------------------
// Prep (E only): row norms + fp32->bf16 conversion. One warp per code row.
// ---------------------------------------------------------------------------
__global__ void enorm_kernel(const float* __restrict__ E) {
    int k    = (blockIdx.x * blockDim.x + threadIdx.x) >> 5;
    int lane = threadIdx.x & 31;
    if (k >= K_) return;
    const float4* p = (const float4*)(E + (size_t)k * D_);
    float4 a = p[lane], b = p[lane + 32];
    __nv_bfloat162* eb = (__nv_bfloat162*)g_ebf;
    eb[k*128 + 2*lane + 0]  = __float22bfloat162_rn(make_float2(a.x, a.y));
    eb[k*128 + 2*lane + 1]  = __float22bfloat162_rn(make_float2(a.z, a.w));
    eb[k*128 + 64 + 2*lane] = __float22bfloat162_rn(make_float2(b.x, b.y));
    eb[k*128 + 65 + 2*lane] = __float22bfloat162_rn(make_float2(b.z, b.w));
    float s = a.x*a.x + a.y*a.y + a.z*a.z + a.w*a.w
            + b.x*b.x + b.y*b.y + b.z*b.z + b.w*b.w;
#pragma unroll
    for (int o = 16; o; o >>= 1) s += __shfl_xor_sync(0xffffffffu, s, o);
    if (lane == 0) g_enorm[k] = s;
}

__global__ void zero_kernel() {
    int t = threadIdx.x;
    g_counts[t] = 0;
    if (t == 0) g_loss = 0.0;
}

// ---------------------------------------------------------------------------
// Main: bf16 mma.sync distance GEMM + windowed candidate capture into a
// per-row shared pool. X norms computed in-flight during the X fill.
// Epilogue keeps a v1th = v1 + WINDOW register to shorten the compare chain.
// ---------------------------------------------------------------------------
__global__ __launch_bounds__(128)
void vq_mma_kernel(const float* __restrict__ X) {
    extern __shared__ char smem[];
    const uint32_t sb = smem_u32(smem);
    const int tid  = threadIdx.x;
    const int wid  = tid >> 5;
    const int lane = tid & 31;
    const int row0 = blockIdx.x * 128;
    const int gid  = lane >> 2;        // 0..7
    const int tig  = lane & 3;         // 0..3

    int*   scnt  = (int*)(smem + SM_CNT);
    int*   spool = (int*)(smem + SM_POOL);
    float* sxn   = (float*)(smem + SM_XN);
    if (tid < 128) scnt[tid] = 0;

    // ---- fill X tile (fp32 -> bf16, XOR-swizzled) + in-flight row norms ----
#pragma unroll 4
    for (int it = 0; it < 32; ++it) {
        int v  = it * 128 + tid;
        int r  = v >> 5;               // uniform across the warp
        int cv = v & 31;
        const float4* gp = (const float4*)(X + (size_t)(row0 + r) * D_ + cv * 8);
        float4 A = gp[0], B = gp[1];
        __nv_bfloat162 h0 = __float22bfloat162_rn(make_float2(A.x, A.y));
        __nv_bfloat162 h1 = __float22bfloat162_rn(make_float2(A.z, A.w));
        __nv_bfloat162 h2 = __float22bfloat162_rn(make_float2(B.x, B.y));
        __nv_bfloat162 h3 = __float22bfloat162_rn(make_float2(B.z, B.w));
        uint32_t off = (uint32_t)(r * 512) + (((uint32_t)(cv * 16)) ^ (((uint32_t)(r & 7)) << 4));
        STS128(sb + SM_X + off, *(uint32_t*)&h0, *(uint32_t*)&h1, *(uint32_t*)&h2, *(uint32_t*)&h3);
        float s = A.x*A.x + A.y*A.y + A.z*A.z + A.w*A.w
                + B.x*B.x + B.y*B.y + B.z*B.z + B.w*B.w;
#pragma unroll
        for (int o = 16; o; o >>= 1) s += __shfl_xor_sync(0xffffffffu, s, o);
        if (lane == 0) { sxn[r] = s; g_xnorm[row0 + r] = s; }
    }

    const uint32_t swz     = ((uint32_t)(lane & 7)) << 4;
    const int      rowoffA = (lane & 7) + 8 * ((lane >> 3) & 1);
    const uint32_t kboffA  = 16u * (uint32_t)(lane >> 4);
    const int      rowoffB = (lane & 7) + 8 * (lane >> 4);
    const uint32_t kboffB  = 16u * (uint32_t)((lane >> 3) & 1);

    uint32_t aBase[2], bBase[4];
#pragma unroll
    for (int mb = 0; mb < 2; ++mb)
        aBase[mb] = sb + SM_X + (uint32_t)((wid * 32 + mb * 16 + rowoffA) * 512);
#pragma unroll
    for (int p = 0; p < 4; ++p)
        bBase[p] = sb + SM_E + (uint32_t)((p * 16 + rowoffB) * 512);

    __syncthreads();   // sxn + X tile visible to all

    float v1[4], v1th[4];
    int   i1[4];
    float xn[4];
    int   rl[4];
#pragma unroll
    for (int t = 0; t < 4; ++t) {
        rl[t]   = wid * 32 + (t >> 1) * 16 + (t & 1) * 8 + gid;
        v1[t]   = FLT_MAX;
        v1th[t] = FLT_MAX;
        i1[t]   = 0;
        xn[t]   = sxn[rl[t]];
    }
    float* ens = (float*)(smem + SM_EN);

    for (int nt = 0; nt < 16; ++nt) {
        __syncthreads();
#pragma unroll 4
        for (int it = 0; it < 16; ++it) {
            int v  = it * 128 + tid;
            int r  = v >> 5;
            int cv = v & 31;
            uint4 w = ((const uint4*)(g_ebf + (size_t)(nt * 64 + r) * D_))[cv];
            uint32_t off = (uint32_t)(r * 512) + (((uint32_t)(cv * 16)) ^ (((uint32_t)(r & 7)) << 4));
            STS128(sb + SM_E + off, w.x, w.y, w.z, w.w);
        }
        if (tid < 64) ens[tid] = g_enorm[nt * 64 + tid];
        __syncthreads();

        float acc[2][8][4];
#pragma unroll
        for (int mb = 0; mb < 2; ++mb)
#pragma unroll
            for (int nb = 0; nb < 8; ++nb)
#pragma unroll
                for (int q = 0; q < 4; ++q) acc[mb][nb][q] = 0.f;

#pragma unroll
        for (int s = 0; s < 16; ++s) {
            uint32_t a[2][4], b[4][4];
            uint32_t offA = ((uint32_t)(32 * s) + kboffA) ^ swz;
            uint32_t offB = ((uint32_t)(32 * s) + kboffB) ^ swz;
#pragma unroll
            for (int mb = 0; mb < 2; ++mb)
                LDSM_X4(a[mb][0], a[mb][1], a[mb][2], a[mb][3], aBase[mb] + offA);
#pragma unroll
            for (int p = 0; p < 4; ++p)
                LDSM_X4(b[p][0], b[p][1], b[p][2], b[p][3], bBase[p] + offB);
#pragma unroll
            for (int mb = 0; mb < 2; ++mb)
#pragma unroll
                for (int p = 0; p < 4; ++p) {
                    MMA_BF16(acc[mb][2*p + 0], a[mb], &b[p][0]);
                    MMA_BF16(acc[mb][2*p + 1], a[mb], &b[p][2]);
                }
        }

#pragma unroll
        for (int nb = 0; nb < 8; ++nb) {
            float2 enp = *(const float2*)&ens[nb * 8 + 2 * tig];
#pragma unroll
            for (int mb = 0; mb < 2; ++mb) {
#pragma unroll
                for (int h = 0; h < 2; ++h) {
                    int t = mb * 2 + h;
#pragma unroll
                    for (int q = 0; q < 2; ++q) {
                        int   code = nt * 64 + nb * 8 + 2 * tig + q;
                        float en   = q ? enp.y : enp.x;
                        float a0   = acc[mb][nb][h * 2 + q];
                        float dist = __fadd_rn(__fadd_rn(xn[t], en), -2.0f * a0);
                        if (dist < v1th[t]) {
                            if (dist < v1[t]) {
                                if (v1[t] < dist + WINDOW) {
                                    int p = atomicAdd(&scnt[rl[t]], 1);
                                    if (p < CAPR) spool[rl[t] * CAPR + p] = i1[t];
                                }
                                v1[t]   = dist;
                                v1th[t] = dist + WINDOW;
                                i1[t]   = code;
                            } else {
                                int p = atomicAdd(&scnt[rl[t]], 1);
                                if (p < CAPR) spool[rl[t] * CAPR + p] = code;
                            }
                        }
                    }
                }
            }
        }
    }

    // ---- merge across the 4 lanes (tig) sharing each row ----
#pragma unroll
    for (int t = 0; t < 4; ++t) {
        int   row = row0 + rl[t];
        float myv = v1[t];
        int   myi = i1[t];
        float bv  = myv;
        int   bi  = myi;
#pragma unroll
        for (int off = 1; off <= 2; off <<= 1) {
            float vv = __shfl_xor_sync(0xffffffffu, bv, off);
            int   ii = __shfl_xor_sync(0xffffffffu, bi, off);
            if (vv < bv || (vv == bv && ii < bi)) { bv = vv; bi = ii; }
        }
        if (myi != bi && myv < bv + WINDOW) {   // losing lane best within window
            int p = atomicAdd(&scnt[rl[t]], 1);
            if (p < CAPR) spool[rl[t] * CAPR + p] = myi;
        }
        if (tig == 0) g_best_i[row] = bi;
    }
    __syncthreads();
    if (tid < 128) {
        int row = row0 + tid;
        int n   = scnt[tid];
        g_ncand[row] = n;
        int m = n < CAPR ? n : CAPR;
        for (int k = 0; k < m; ++k)
            g_cand[(size_t)row * CAPR + k] = spool[tid * CAPR + k];
    }
}

// ---------------------------------------------------------------------------
// Recheck + gather + loss. 1 warp handles TWO rows interleaved. Batched exact
// fp32 candidate evals, identical argmin semantics.
// ---------------------------------------------------------------------------
__global__ __launch_bounds__(256) void recheck_kernel(const float* __restrict__ X,
                                                      const float* __restrict__ E,
                                                      float* __restrict__ outq,
                                                      float* __restrict__ out_idx) {
    __shared__ double lsum[8];
    const int tid  = threadIdx.x;
    const int w    = tid >> 5;
    const int lane = tid & 31;
    const int r0   = blockIdx.x * 16 + w * 2;
    const int r1   = r0 + 1;

    const float4* xr0 = (const float4*)(X + (size_t)r0 * D_);
    const float4* xr1 = (const float4*)(X + (size_t)r1 * D_);
    float4 xa0 = xr0[lane * 2], xb0 = xr0[lane * 2 + 1];
    float4 xa1 = xr1[lane * 2], xb1 = xr1[lane * 2 + 1];
    int n0  = g_ncand[r0],  n1  = g_ncand[r1];
    int bi0 = g_best_i[r0], bi1 = g_best_i[r1];

    auto recheck_row = [&](int row, int n, int bi, float4 xa, float4 xb) -> int {
        float xn = g_xnorm[row];
        float bv = FLT_MAX;
        int   bb = 0x7fffffff;
        int   hi   = (n <= CAPR) ? (n + 1) : K_;
        bool  pool = (n <= CAPR);
        const int* gc = g_cand + (size_t)row * CAPR;
        for (int b0 = 0; b0 < hi; b0 += 8) {
            int   c[8];
            float p[8];
#pragma unroll
            for (int j = 0; j < 8; ++j) {
                int idx = b0 + j;
                c[j] = pool ? ((idx < n) ? gc[idx] : bi)
                            : ((idx < K_) ? idx : 0);
                const float4* er = (const float4*)(E + (size_t)c[j] * D_);
                float4 ea = er[lane * 2], eb = er[lane * 2 + 1];
                p[j] = xa.x*ea.x + xa.y*ea.y + xa.z*ea.z + xa.w*ea.w
                     + xb.x*eb.x + xb.y*eb.y + xb.z*eb.z + xb.w*eb.w;
            }
#pragma unroll
            for (int o = 16; o; o >>= 1) {
#pragma unroll
                for (int j = 0; j < 8; ++j)
                    p[j] += __shfl_xor_sync(0xffffffffu, p[j], o);
            }
#pragma unroll
            for (int j = 0; j < 8; ++j) {
                if (b0 + j < hi) {
                    float d = __fadd_rn(__fadd_rn(xn, g_enorm[c[j]]), -2.0f * p[j]);
                    if (d < bv || (d == bv && c[j] < bb)) { bv = d; bb = c[j]; }
                }
            }
        }
        return bb;
    };

    if (n0 > 0) bi0 = recheck_row(r0, n0, bi0, xa0, xb0);
    if (n1 > 0) bi1 = recheck_row(r1, n1, bi1, xa1, xb1);

    const float4* er0 = (const float4*)(E + (size_t)bi0 * D_);
    const float4* er1 = (const float4*)(E + (size_t)bi1 * D_);
    float4 ea0 = er0[lane * 2], eb0 = er0[lane * 2 + 1];
    float4 ea1 = er1[lane * 2], eb1 = er1[lane * 2 + 1];

    float s = 0.f;
    {
        float4 d0, o0, d1, o1;
        d0.x = __fadd_rn(ea0.x, -xa0.x); o0.x = __fadd_rn(xa0.x, d0.x);
        d0.y = __fadd_rn(ea0.y, -xa0.y); o0.y = __fadd_rn(xa0.y, d0.y);
        d0.z = __fadd_rn(ea0.z, -xa0.z); o0.z = __fadd_rn(xa0.z, d0.z);
        d0.w = __fadd_rn(ea0.w, -xa0.w); o0.w = __fadd_rn(xa0.w, d0.w);
        d1.x = __fadd_rn(eb0.x, -xb0.x); o1.x = __fadd_rn(xb0.x, d1.x);
        d1.y = __fadd_rn(eb0.y, -xb0.y); o1.y = __fadd_rn(xb0.y, d1.y);
        d1.z = __fadd_rn(eb0.z, -xb0.z); o1.z = __fadd_rn(xb0.z, d1.z);
        d1.w = __fadd_rn(eb0.w, -xb0.w); o1.w = __fadd_rn(xb0.w, d1.w);
        float4* oq = (float4*)(outq + (size_t)r0 * D_);
        oq[lane * 2]     = o0;
        oq[lane * 2 + 1] = o1;
        s += d0.x*d0.x + d0.y*d0.y + d0.z*d0.z + d0.w*d0.w
           + d1.x*d1.x + d1.y*d1.y + d1.z*d1.z + d1.w*d1.w;
    }
    {
        float4 d0, o0, d1, o1;
        d0.x = __fadd_rn(ea1.x, -xa1.x); o0.x = __fadd_rn(xa1.x, d0.x);
        d0.y = __fadd_rn(ea1.y, -xa1.y); o0.y = __fadd_rn(xa1.y, d0.y);
        d0.z = __fadd_rn(ea1.z, -xa1.z); o0.z = __fadd_rn(xa1.z, d0.z);
        d0.w = __fadd_rn(ea1.w, -xa1.w); o0.w = __fadd_rn(xa1.w, d0.w);
        d1.x = __fadd_rn(eb1.x, -xb1.x); o1.x = __fadd_rn(xb1.x, d1.x);
        d1.y = __fadd_rn(eb1.y, -xb1.y); o1.y = __fadd_rn(xb1.y, d1.y);
        d1.z = __fadd_rn(eb1.z, -xb1.z); o1.z = __fadd_rn(xb1.z, d1.z);
        d1.w = __fadd_rn(eb1.w, -xb1.w); o1.w = __fadd_rn(xb1.w, d1.w);
        float4* oq = (float4*)(outq + (size_t)r1 * D_);
        oq[lane * 2]     = o0;
        oq[lane * 2 + 1] = o1;
        s += d0.x*d0.x + d0.y*d0.y + d0.z*d0.z + d0.w*d0.w
           + d1.x*d1.x + d1.y*d1.y + d1.z*d1.z + d1.w*d1.w;
    }
#pragma unroll
    for (int o = 16; o; o >>= 1) s += __shfl_xor_sync(0xffffffffu, s, o);
    if (lane == 0) {
        lsum[w] = (double)s;
        out_idx[r0] = (float)bi0;
        out_idx[r1] = (float)bi1;
        atomicAdd(&g_counts[bi0], 1);
        atomicAdd(&g_counts[bi1], 1);
    }
    __syncthreads();
    if (tid == 0) {
        double t = 0.0;
#pragma unroll
        for (int i = 0; i < 8; ++i) t += lsum[i];
        atomicAdd(&g_loss, t);
    }
}

// ---------------------------------------------------------------------------
__global__ void final_kernel(float* __restrict__ out_tail) {
    __shared__ float sh[32];
    int t = threadIdx.x;
    float p = (float)g_counts[t] * (1.0f / (float)BN_);
    float term = p * logf(p + 1.1920929e-07f);
#pragma unroll
    for (int o = 16; o; o >>= 1) term += __shfl_xor_sync(0xffffffffu, term, o);
    if ((t & 31) == 0) sh[t >> 5] = term;
    __syncthreads();
    if (t < 32) {
        float v = sh[t];
#pragma unroll
        for (int o = 16; o; o >>= 1) v += __shfl_xor_sync(0xffffffffu, v, o);
        if (t == 0) {
            out_tail[0] = expf(-v);
            out_tail[1] = (float)(g_loss * (1.1 / (double)((size_t)BN_ * D_)));
        }
    }
}

// ---------------------------------------------------------------------------
extern "C" void kernel_launch(void* const* d_in, const int* in_sizes, int n_in,
                              void* d_out, int out_size) {
    const float* X = (const float*)d_in[0];
    const float* E = (const float*)d_in[1];
    float* out      = (float*)d_out;
    float* out_idx  = out + (size_t)BN_ * D_;
    float* out_tail = out_idx + BN_;

    cudaFuncSetAttribute(vq_mma_kernel, cudaFuncAttributeMaxDynamicSharedMemorySize, SMEM_BYTES);

    enorm_kernel<<<K_ / 8, 256>>>(E);
    zero_kernel<<<1, K_>>>();
    vq_mma_kernel<<<BN_ / 128, 128, SMEM_BYTES>>>(X);
    recheck_kernel<<<BN_ / 16, 256>>>(X, E, out, out_idx);
    final_kernel<<<1, K_>>>(out_tail);
}